// round 2
// baseline (speedup 1.0000x reference)
#include <cuda_runtime.h>
#include <cuda_bf16.h>
#include <math.h>

#define BB 2
#define HH 128
#define WW 128
#define HW (HH*WW)
#define DIM 128
#define NH 8
#define HD 16
#define KA2 9

typedef unsigned long long ull;

// Scratch (device globals; allocation-free rule)
__device__ float g_E[BB * 19 * HW];          // extras: 0-7 cond, 8 lpan, 9 pan, 10 pan-lpan, 11-18 ms
__device__ float g_OUT[BB * 640 * HW];       // 0-127 q(scaled), 128-255 k_pan, 256-383 v_pan, 384-511 k_ms, 512-639 v_ms
__device__ float g_ATT[BB * 2 * DIM * HW];   // attention output (b, s, c, hw)

// ---------------------------------------------------------------------------
// f32x2 packed-math helpers (sm_103a FFMA2 path; ptxas never emits these)
// ---------------------------------------------------------------------------
__device__ __forceinline__ ull pk2(float lo, float hi) {
    ull r;
    asm("mov.b64 %0, {%1, %2};" : "=l"(r) : "f"(lo), "f"(hi));
    return r;
}
__device__ __forceinline__ ull fma2(ull a, ull b, ull c) {
    ull d;
    asm("fma.rn.f32x2 %0, %1, %2, %3;" : "=l"(d) : "l"(a), "l"(b), "l"(c));
    return d;
}
__device__ __forceinline__ float2 upk(ull v) {
    float2 f;
    asm("mov.b64 {%0, %1}, %2;" : "=f"(f.x), "=f"(f.y) : "l"(v));
    return f;
}

// ---------------------------------------------------------------------------
// Pack the non-x input channels
// ---------------------------------------------------------------------------
__global__ void pack_kernel(const float* __restrict__ ms,
                            const float* __restrict__ lpan,
                            const float* __restrict__ pan,
                            const float* __restrict__ s)
{
    int idx = blockIdx.x * blockDim.x + threadIdx.x;
    if (idx >= BB * HW) return;
    int b = idx / HW;
    int p = idx % HW;
    float sv = s[b];
    float lp = lpan[b * HW + p];
    float pn = pan[b * HW + p];
    float* Eb = g_E + b * 19 * HW;
#pragma unroll
    for (int c = 0; c < 8; c++) {
        float m = ms[(b * 8 + c) * HW + p];
        Eb[c * HW + p]        = lp * (1.0f - sv) + m * sv;   // cond
        Eb[(11 + c) * HW + p] = m;                            // ms copy
    }
    Eb[8 * HW + p]  = lp;
    Eb[9 * HW + p]  = pn;
    Eb[10 * HW + p] = pn - lp;
}

// ---------------------------------------------------------------------------
// 3x3 conv, FFMA2 version.
// Block: 32x16 px x 32 oc, 256 threads. Thread: 2(row)x4(col) px x 8 oc.
// Channel chunks of 8 through shared memory.
// ---------------------------------------------------------------------------
#define CC 8
__global__ __launch_bounds__(256) void conv3x3_kernel(
    const float* __restrict__ x,
    const float* __restrict__ wt,
    const float* __restrict__ bias,
    int cin, int extra_base, int out_off, float scale)
{
    __shared__ float s_in[CC][18][36];   // 34 cols used (+2 pad)
    __shared__ float s_w[CC][32][9];

    int b   = blockIdx.z;
    int tx0 = (blockIdx.x & 3) * 32;
    int ty0 = (blockIdx.x >> 2) * 16;
    int ocb = blockIdx.y * 32;
    int t   = threadIdx.x;
    int pg  = t & 63;
    int og  = t >> 6;          // 4 oc groups of 8
    int gx  = (pg & 7) * 4;    // 0..28
    int gy  = (pg >> 3) * 2;   // 0..14

    const float* xb = x + b * 128 * HW;
    const float* Eb = g_E + b * 19 * HW;

    ull acc[2][2][8];
#pragma unroll
    for (int py = 0; py < 2; py++)
#pragma unroll
        for (int pr = 0; pr < 2; pr++)
#pragma unroll
            for (int o = 0; o < 8; o++) acc[py][pr][o] = 0ULL;

    for (int c0 = 0; c0 < cin; c0 += CC) {
        // ---- load input tile: CC channels x 18 rows x 34 cols, zero-padded
        for (int i = t; i < CC * 18 * 34; i += 256) {
            int cc = i / (18 * 34);
            int r  = i % (18 * 34);
            int iy = r / 34, ix = r % 34;
            int c  = c0 + cc;
            int yy = ty0 - 1 + iy, xx = tx0 - 1 + ix;
            float v = 0.0f;
            if (c < cin && yy >= 0 && yy < HH && xx >= 0 && xx < WW) {
                const float* src = (c < 128) ? (xb + c * HW)
                                             : (Eb + (extra_base + (c - 128)) * HW);
                v = src[yy * WW + xx];
            }
            s_in[cc][iy][ix] = v;
        }
        // ---- load weights: CC x 32 oc x 9
        for (int i = t; i < CC * 32 * 9; i += 256) {
            int cc  = i / 288;
            int rem = i % 288;
            int o   = rem / 9;
            int k   = rem % 9;
            int c   = c0 + cc;
            s_w[cc][o][k] = (c < cin) ? wt[((ocb + o) * cin + c) * 9 + k] : 0.0f;
        }
        __syncthreads();

#pragma unroll 2
        for (int cc = 0; cc < CC; cc++) {
            ull q0[5], q1[5];
            // rolling 2-row window of overlapping pairs
            {
                const float* rp = &s_in[cc][gy + 0][gx];
                float4 a = *(const float4*)rp;
                float2 bb2 = *(const float2*)(rp + 4);
                q0[0] = pk2(a.x, a.y); q0[1] = pk2(a.y, a.z); q0[2] = pk2(a.z, a.w);
                q0[3] = pk2(a.w, bb2.x); q0[4] = pk2(bb2.x, bb2.y);
            }
            {
                const float* rp = &s_in[cc][gy + 1][gx];
                float4 a = *(const float4*)rp;
                float2 bb2 = *(const float2*)(rp + 4);
                q1[0] = pk2(a.x, a.y); q1[1] = pk2(a.y, a.z); q1[2] = pk2(a.z, a.w);
                q1[3] = pk2(a.w, bb2.x); q1[4] = pk2(bb2.x, bb2.y);
            }
            // ky = 0: py0 uses row gy+0 (q0), py1 uses row gy+1 (q1)
#pragma unroll
            for (int o = 0; o < 8; o++) {
                const float* wp = &s_w[cc][og * 8 + o][0];
#pragma unroll
                for (int kx = 0; kx < 3; kx++) {
                    ull w2 = pk2(wp[kx], wp[kx]);
                    acc[0][0][o] = fma2(w2, q0[kx],     acc[0][0][o]);
                    acc[0][1][o] = fma2(w2, q0[kx + 2], acc[0][1][o]);
                    acc[1][0][o] = fma2(w2, q1[kx],     acc[1][0][o]);
                    acc[1][1][o] = fma2(w2, q1[kx + 2], acc[1][1][o]);
                }
            }
            // load row gy+2 into q0
            {
                const float* rp = &s_in[cc][gy + 2][gx];
                float4 a = *(const float4*)rp;
                float2 bb2 = *(const float2*)(rp + 4);
                q0[0] = pk2(a.x, a.y); q0[1] = pk2(a.y, a.z); q0[2] = pk2(a.z, a.w);
                q0[3] = pk2(a.w, bb2.x); q0[4] = pk2(bb2.x, bb2.y);
            }
            // ky = 1: py0 row gy+1 (q1), py1 row gy+2 (q0)
#pragma unroll
            for (int o = 0; o < 8; o++) {
                const float* wp = &s_w[cc][og * 8 + o][3];
#pragma unroll
                for (int kx = 0; kx < 3; kx++) {
                    ull w2 = pk2(wp[kx], wp[kx]);
                    acc[0][0][o] = fma2(w2, q1[kx],     acc[0][0][o]);
                    acc[0][1][o] = fma2(w2, q1[kx + 2], acc[0][1][o]);
                    acc[1][0][o] = fma2(w2, q0[kx],     acc[1][0][o]);
                    acc[1][1][o] = fma2(w2, q0[kx + 2], acc[1][1][o]);
                }
            }
            // load row gy+3 into q1
            {
                const float* rp = &s_in[cc][gy + 3][gx];
                float4 a = *(const float4*)rp;
                float2 bb2 = *(const float2*)(rp + 4);
                q1[0] = pk2(a.x, a.y); q1[1] = pk2(a.y, a.z); q1[2] = pk2(a.z, a.w);
                q1[3] = pk2(a.w, bb2.x); q1[4] = pk2(bb2.x, bb2.y);
            }
            // ky = 2: py0 row gy+2 (q0), py1 row gy+3 (q1)
#pragma unroll
            for (int o = 0; o < 8; o++) {
                const float* wp = &s_w[cc][og * 8 + o][6];
#pragma unroll
                for (int kx = 0; kx < 3; kx++) {
                    ull w2 = pk2(wp[kx], wp[kx]);
                    acc[0][0][o] = fma2(w2, q0[kx],     acc[0][0][o]);
                    acc[0][1][o] = fma2(w2, q0[kx + 2], acc[0][1][o]);
                    acc[1][0][o] = fma2(w2, q1[kx],     acc[1][0][o]);
                    acc[1][1][o] = fma2(w2, q1[kx + 2], acc[1][1][o]);
                }
            }
        }
        __syncthreads();
    }

    // ---- epilogue
#pragma unroll
    for (int o = 0; o < 8; o++) {
        int oc = ocb + og * 8 + o;
        float bs = bias[oc];
        float* base = g_OUT + (size_t)(b * 640 + out_off + oc) * HW;
#pragma unroll
        for (int py = 0; py < 2; py++) {
            int y = ty0 + gy + py;
#pragma unroll
            for (int pr = 0; pr < 2; pr++) {
                int xo = tx0 + gx + pr * 2;
                float2 v = upk(acc[py][pr][o]);
                float2 outv;
                outv.x = (v.x + bs) * scale;
                outv.y = (v.y + bs) * scale;
                *(float2*)(base + y * WW + xo) = outv;
            }
        }
    }
}

// ---------------------------------------------------------------------------
// Fused depthwise conv (16 groups x 9 filters) + logits + softmax + V
// ---------------------------------------------------------------------------
__global__ __launch_bounds__(256) void attn_kernel(const float* __restrict__ dep_w,
                                                   const float* __restrict__ dep_b)
{
    __shared__ float s_raw[16][18 * 20];
    __shared__ float s_dw[144][9];
    __shared__ float s_db[144];

    int b    = blockIdx.z;
    int sn   = blockIdx.y;
    int sidx = sn >> 3;
    int n    = sn & 7;
    int ty0  = (blockIdx.x >> 3) * 16;
    int tx0  = (blockIdx.x & 7) * 16;
    int t    = threadIdx.x;
    int ly   = t >> 4, lx = t & 15;
    int Y    = ty0 + ly, X = tx0 + lx;

    for (int i = t; i < 144 * 9; i += 256) s_dw[i / 9][i % 9] = dep_w[i];
    if (t < 144) s_db[t] = dep_b[t];

    int kbase = (sidx == 0 ? 128 : 384) + n * 16;
    int vbase = (sidx == 0 ? 256 : 512) + n * 16;
    const float* Ob = g_OUT + b * 640 * HW;

    for (int i = t; i < 16 * 324; i += 256) {
        int d  = i / 324;
        int r  = i % 324;
        int iy = r / 18, ix = r % 18;
        int yy = ty0 - 1 + iy, xx = tx0 - 1 + ix;
        float v = 0.0f;
        if (yy >= 0 && yy < HH && xx >= 0 && xx < WW)
            v = Ob[(kbase + d) * HW + yy * WW + xx];
        s_raw[d][iy * 20 + ix] = v;
    }
    __syncthreads();

    float logit[9];
#pragma unroll
    for (int a = 0; a < 9; a++) logit[a] = 0.0f;

#pragma unroll 4
    for (int d = 0; d < 16; d++) {
        float qd = Ob[(n * 16 + d) * HW + Y * WW + X];
        float tap[9];
#pragma unroll
        for (int ky = 0; ky < 3; ky++)
#pragma unroll
            for (int kx = 0; kx < 3; kx++)
                tap[ky * 3 + kx] = s_raw[d][(ly + ky) * 20 + lx + kx];
#pragma unroll
        for (int a = 0; a < 9; a++) {
            float kda = s_db[d * 9 + a];
#pragma unroll
            for (int k = 0; k < 9; k++) kda += s_dw[d * 9 + a][k] * tap[k];
            logit[a] += qd * kda;
        }
    }

    float m = logit[0];
#pragma unroll
    for (int a = 1; a < 9; a++) m = fmaxf(m, logit[a]);
    float attn[9];
    float sum = 0.0f;
#pragma unroll
    for (int a = 0; a < 9; a++) { attn[a] = __expf(logit[a] - m); sum += attn[a]; }
    float inv = 1.0f / sum;
#pragma unroll
    for (int a = 0; a < 9; a++) attn[a] *= inv;

    __syncthreads();
    for (int i = t; i < 16 * 324; i += 256) {
        int d  = i / 324;
        int r  = i % 324;
        int iy = r / 18, ix = r % 18;
        int yy = ty0 - 1 + iy, xx = tx0 - 1 + ix;
        float v = 0.0f;
        if (yy >= 0 && yy < HH && xx >= 0 && xx < WW)
            v = Ob[(vbase + d) * HW + yy * WW + xx];
        s_raw[d][iy * 20 + ix] = v;
    }
    __syncthreads();

    float* outp = g_ATT + ((b * 2 + sidx) * DIM + n * 16) * HW + Y * WW + X;
#pragma unroll 4
    for (int d = 0; d < 16; d++) {
        float tap[9];
#pragma unroll
        for (int ky = 0; ky < 3; ky++)
#pragma unroll
            for (int kx = 0; kx < 3; kx++)
                tap[ky * 3 + kx] = s_raw[d][(ly + ky) * 20 + lx + kx];
        float outd = 0.0f;
#pragma unroll
        for (int a = 0; a < 9; a++) {
            float vda = s_db[d * 9 + a];
#pragma unroll
            for (int k = 0; k < 9; k++) vda += s_dw[d * 9 + a][k] * tap[k];
            outd += attn[a] * vda;
        }
        outp[d * HW] = outd;
    }
}

// ---------------------------------------------------------------------------
// 1x1 projection: 64 pixels x 128 oc per block
// ---------------------------------------------------------------------------
__global__ __launch_bounds__(256) void proj_kernel(const float* __restrict__ wt,
                                                   const float* __restrict__ bias,
                                                   int sidx, float* __restrict__ out)
{
    __shared__ float s_w[32][128];
    __shared__ float s_in[32][64];

    int b  = blockIdx.y;
    int p0 = blockIdx.x * 64;
    int t  = threadIdx.x;
    int pg = t & 31;
    int og = t >> 5;

    float acc0[16], acc1[16];
#pragma unroll
    for (int o = 0; o < 16; o++) { acc0[o] = 0.0f; acc1[o] = 0.0f; }

    const float* inb = g_ATT + (b * 2 + sidx) * DIM * HW;

    for (int c0 = 0; c0 < 128; c0 += 32) {
        for (int i = t; i < 32 * 128; i += 256) {
            int cc = i >> 7;
            int oc = i & 127;
            s_w[cc][oc] = wt[oc * 128 + c0 + cc];
        }
        for (int i = t; i < 32 * 64; i += 256) {
            int cc = i >> 6;
            int pp = i & 63;
            s_in[cc][pp] = inb[(c0 + cc) * HW + p0 + pp];
        }
        __syncthreads();
#pragma unroll
        for (int cc = 0; cc < 32; cc++) {
            float i0 = s_in[cc][pg * 2];
            float i1 = s_in[cc][pg * 2 + 1];
#pragma unroll
            for (int o = 0; o < 16; o++) {
                float wv = s_w[cc][og * 16 + o];
                acc0[o] += i0 * wv;
                acc1[o] += i1 * wv;
            }
        }
        __syncthreads();
    }
#pragma unroll
    for (int o = 0; o < 16; o++) {
        int oc = og * 16 + o;
        float bs = bias[oc];
        out[(b * 128 + oc) * HW + p0 + pg * 2]     = acc0[o] + bs;
        out[(b * 128 + oc) * HW + p0 + pg * 2 + 1] = acc1[o] + bs;
    }
}

// ---------------------------------------------------------------------------
extern "C" void kernel_launch(void* const* d_in, const int* in_sizes, int n_in,
                              void* d_out, int out_size)
{
    const float* x        = (const float*)d_in[0];
    const float* ms       = (const float*)d_in[1];
    const float* lpan     = (const float*)d_in[2];
    const float* pan      = (const float*)d_in[3];
    const float* s        = (const float*)d_in[4];
    const float* q_w      = (const float*)d_in[5];
    const float* q_b      = (const float*)d_in[6];
    const float* k_pan_w  = (const float*)d_in[7];
    const float* k_pan_b  = (const float*)d_in[8];
    const float* v_pan_w  = (const float*)d_in[9];
    const float* v_pan_b  = (const float*)d_in[10];
    const float* kv_ms_w  = (const float*)d_in[11];
    const float* kv_ms_b  = (const float*)d_in[12];
    const float* dep_w    = (const float*)d_in[13];
    const float* dep_b    = (const float*)d_in[14];
    const float* ppan_w   = (const float*)d_in[15];
    const float* ppan_b   = (const float*)d_in[16];
    const float* pms_w    = (const float*)d_in[17];
    const float* pms_b    = (const float*)d_in[18];
    float* out = (float*)d_out;

    const float SCALE = 0.25f;   // HD^-0.5 = 16^-0.5

    pack_kernel<<<(BB * HW + 255) / 256, 256>>>(ms, lpan, pan, s);

    dim3 cg(32, 4, BB);
    conv3x3_kernel<<<cg, 256>>>(x, q_w,     q_b,     136, 0,  0,   SCALE);
    conv3x3_kernel<<<cg, 256>>>(x, k_pan_w, k_pan_b, 129, 8,  128, 1.0f);
    conv3x3_kernel<<<cg, 256>>>(x, v_pan_w, v_pan_b, 131, 8,  256, 1.0f);
    dim3 cg2(32, 8, BB);
    conv3x3_kernel<<<cg2, 256>>>(x, kv_ms_w, kv_ms_b, 136, 11, 384, 1.0f);

    dim3 ag(64, 16, BB);
    attn_kernel<<<ag, 256>>>(dep_w, dep_b);

    dim3 pg(HW / 64, BB);
    proj_kernel<<<pg, 256>>>(ppan_w, ppan_b, 0, out);
    proj_kernel<<<pg, 256>>>(pms_w,  pms_b,  1, out + BB * DIM * HW);
}

// round 4
// speedup vs baseline: 3.1286x; 3.1286x over previous
#include <cuda_runtime.h>
#include <cuda_bf16.h>
#include <cstdint>
#include <math.h>

#define BB 2
#define HH 128
#define WW 128
#define HW (HH*WW)
#define DIM 128
#define NH 8
#define HD 16

#define CPAD 160            // unified channel count (147 used, padded)
#define PW 130              // padded image width/height
#define NPIX (PW*PW)

// ---------------- device scratch (allocation-free rule) ----------------
__device__ float g_XT[BB * NPIX * CPAD];       // padded tf32 activations [pix][ch]
__device__ float g_WU[5 * 45 * 4096];          // fragment-ordered tf32 weights
__device__ float g_WB[640];                    // biases
__device__ float g_OUT[BB * 640 * HW];         // q | k_pan | v_pan | k_ms | v_ms
__device__ float g_ATT[BB * 2 * DIM * HW];     // attention output

__device__ __forceinline__ float tf32r(float x) {
    uint32_t u;
    asm("cvt.rna.tf32.f32 %0, %1;" : "=r"(u) : "f"(x));
    return __uint_as_float(u);
}

__device__ __forceinline__ void mma_tf32(float* c, const uint32_t* a,
                                         uint32_t b0, uint32_t b1) {
    asm volatile(
        "mma.sync.aligned.m16n8k8.row.col.f32.tf32.tf32.f32 "
        "{%0,%1,%2,%3}, {%4,%5,%6,%7}, {%8,%9}, {%0,%1,%2,%3};"
        : "+f"(c[0]), "+f"(c[1]), "+f"(c[2]), "+f"(c[3])
        : "r"(a[0]), "r"(a[1]), "r"(a[2]), "r"(a[3]), "r"(b0), "r"(b1));
}

// ---------------------------------------------------------------------------
// build_xt: transpose x + derived channels into padded [pix][ch] layout (tf32)
// ---------------------------------------------------------------------------
__global__ __launch_bounds__(256) void build_xt_kernel(
    const float* __restrict__ x, const float* __restrict__ ms,
    const float* __restrict__ lpan, const float* __restrict__ pan,
    const float* __restrict__ s)
{
    __shared__ float st[CPAD][65];
    int b  = blockIdx.y;
    int p0 = blockIdx.x * 64;
    int t  = threadIdx.x;
    float sv = s[b];

    for (int i = t; i < CPAD * 64; i += 256) {
        int c = i >> 6, px = i & 63;
        int p = p0 + px;
        float v = 0.0f;
        if (c < 128)        v = x[(b * 128 + c) * HW + p];
        else if (c < 136) { float lp = lpan[b * HW + p];
                            float m  = ms[(b * 8 + (c - 128)) * HW + p];
                            v = lp * (1.0f - sv) + m * sv; }
        else if (c == 136)  v = lpan[b * HW + p];
        else if (c == 137)  v = pan[b * HW + p];
        else if (c == 138)  v = pan[b * HW + p] - lpan[b * HW + p];
        else if (c < 147)   v = ms[(b * 8 + (c - 139)) * HW + p];
        st[c][px] = tf32r(v);
    }
    __syncthreads();
    for (int i = t; i < 64 * 40; i += 256) {
        int px = i / 40, q = i % 40;
        int p = p0 + px;
        int y = p >> 7, xx = p & 127;
        size_t pidx = (size_t)(y + 1) * PW + (xx + 1);
        float4 o;
        o.x = st[4 * q + 0][px]; o.y = st[4 * q + 1][px];
        o.z = st[4 * q + 2][px]; o.w = st[4 * q + 3][px];
        *(float4*)(g_XT + (size_t)b * NPIX * CPAD + pidx * CPAD + 4 * q) = o;
    }
}

__global__ void zero_border_kernel()
{
    int idx = blockIdx.x * blockDim.x + threadIdx.x;
    if (idx >= BB * NPIX) return;
    int b = idx / NPIX, p = idx % NPIX;
    int py = p / PW, px = p % PW;
    if (py == 0 || py == PW - 1 || px == 0 || px == PW - 1) {
        float4 z = {0.f, 0.f, 0.f, 0.f};
        float4* dst = (float4*)(g_XT + (size_t)b * NPIX * CPAD + (size_t)p * CPAD);
#pragma unroll
        for (int i = 0; i < CPAD / 4; i++) dst[i] = z;
    }
}

// ---------------------------------------------------------------------------
// repack weights into m16n8k8 fragment order:
// g_WU[octile][tap][kc][mfrag(8)][k8(4)][lane(32)][r(4)]
// a-frag mapping: m_local = mfrag*16 + (lane>>2) + (r&1)*8
//                 k_local = kc*32 + k8*8 + (lane&3) + (r>>1)*4
// ---------------------------------------------------------------------------
__global__ void repack_w_kernel(
    const float* __restrict__ qw, const float* __restrict__ kpw,
    const float* __restrict__ vpw, const float* __restrict__ kvw,
    const float* __restrict__ qb, const float* __restrict__ kpb,
    const float* __restrict__ vpb, const float* __restrict__ kvb)
{
    int idx = blockIdx.x * blockDim.x + threadIdx.x;
    if (idx < 640) {
        float bv;
        if (idx < 128)      bv = qb[idx];
        else if (idx < 256) bv = kpb[idx - 128];
        else if (idx < 384) bv = vpb[idx - 256];
        else                bv = kvb[idx - 384];
        g_WB[idx] = bv;
    }
    if (idx >= 5 * 45 * 4096) return;
    int i2 = idx;
    int r     = i2 & 3;  i2 >>= 2;
    int lane  = i2 & 31; i2 >>= 5;
    int k8    = i2 & 3;  i2 >>= 2;
    int mfrag = i2 & 7;  i2 >>= 3;
    int kc    = i2 % 5;  i2 /= 5;
    int tap   = i2 % 9;
    int octile = i2 / 9;

    int m_local = mfrag * 16 + (lane >> 2) + (r & 1) * 8;
    int c       = kc * 32 + k8 * 8 + (lane & 3) + (r >> 1) * 4;
    int oc_g    = octile * 128 + m_local;

    float v = 0.0f;
    if (oc_g < 128) {                               // q : x + cond(128-135)
        if (c < 136) v = qw[(oc_g * 136 + c) * 9 + tap];
    } else if (oc_g < 256) {                        // k_pan : x + lpan(136)
        int oc = oc_g - 128;
        if (c < 128)       v = kpw[(oc * 129 + c) * 9 + tap];
        else if (c == 136) v = kpw[(oc * 129 + 128) * 9 + tap];
    } else if (oc_g < 384) {                        // v_pan : x + 136,137,138
        int oc = oc_g - 256;
        if (c < 128)                  v = vpw[(oc * 131 + c) * 9 + tap];
        else if (c >= 136 && c < 139) v = vpw[(oc * 131 + 128 + (c - 136)) * 9 + tap];
    } else {                                        // kv_ms : x + ms(139-146)
        int oc = oc_g - 384;
        if (c < 128)                  v = kvw[(oc * 136 + c) * 9 + tap];
        else if (c >= 139 && c < 147) v = kvw[(oc * 136 + 128 + (c - 139)) * 9 + tap];
    }
    g_WU[idx] = tf32r(v);
}

// ---------------------------------------------------------------------------
// conv via mma.sync tf32. CTA: 128 oc x 128 px (one image row).
// 8 warps = 2(m) x 4(n); warp tile 64 oc x 32 px.
// 45 K-steps of K=32 (9 taps x 5 channel chunks), double-buffered smem.
// ---------------------------------------------------------------------------
#define CONV_SMEM (2 * 8192 * 4)
__global__ __launch_bounds__(256) void conv_mma_kernel()
{
    extern __shared__ float smem[];   // [2][A:4096 | B:4096] floats
    int t = threadIdx.x;
    int w = t >> 5, lane = t & 31;
    int g = lane >> 2, tt = lane & 3;
    int y0 = blockIdx.x;
    int octile = blockIdx.y;
    int b = blockIdx.z;

    const float* WU  = g_WU + (size_t)octile * 45 * 4096;
    const float* XTb = g_XT + (size_t)b * NPIX * CPAD;

    int mw0 = (w >> 2) * 4;   // warp's mfrag base (0 or 4)
    int n80 = (w & 3) * 4;    // warp's n8 base

    float acc[4][4][4];
#pragma unroll
    for (int mf = 0; mf < 4; mf++)
#pragma unroll
        for (int nf = 0; nf < 4; nf++)
#pragma unroll
            for (int r = 0; r < 4; r++) acc[mf][nf][r] = 0.0f;

    float4 pa[4], pb[4];
    int kq  = t & 7;      // B load: fixed k-quad per thread
    int px0 = t >> 3;     // B load: base pixel

    // ---- prologue: load step 0
    {
        const float* Ws = WU;
        int yy = y0 /*+dy(-1)*/;      // tap 0: dy=-1,dx=-1  => yy = y0-1+1 = y0
#pragma unroll
        for (int j = 0; j < 4; j++) pa[j] = *(const float4*)(Ws + (t + j * 256) * 4);
#pragma unroll
        for (int j = 0; j < 4; j++) {
            int px = px0 + 32 * j;
            pb[j] = *(const float4*)(XTb + ((size_t)yy * PW + px) * CPAD + kq * 4);
        }
        float* S = smem;
#pragma unroll
        for (int j = 0; j < 4; j++) *(float4*)(S + (t + j * 256) * 4) = pa[j];
        float* SB = S + 4096;
        int k8 = kq >> 1, rp = kq & 1;
#pragma unroll
        for (int j = 0; j < 4; j++) {
            int px = px0 + 32 * j;
            int n8 = px >> 3, gg = px & 7;
            *(float4*)(SB + rp * 2048 + ((n8 * 4 + k8) * 32 + gg * 4)) = pb[j];
        }
    }
    __syncthreads();

    for (int step = 0; step < 45; step++) {
        int buf = step & 1;
        // ---- prefetch step+1 into regs
        if (step < 44) {
            int s1 = step + 1;
            int tap = s1 / 5, kc = (s1 % 5) * 32;
            int dy = tap / 3 - 1, dx = tap % 3 - 1;
            const float* Ws = WU + (size_t)s1 * 4096;
#pragma unroll
            for (int j = 0; j < 4; j++) pa[j] = *(const float4*)(Ws + (t + j * 256) * 4);
            int yy = y0 + dy + 1;
#pragma unroll
            for (int j = 0; j < 4; j++) {
                int px = px0 + 32 * j;
                pb[j] = *(const float4*)(XTb + ((size_t)yy * PW + (px + dx + 1) - 1 + 1) * CPAD
                                         + kc + kq * 4);
            }
        }
        // ---- MMA on current buffer
        {
            const float* SA = smem + buf * 8192;
            const float* SB = SA + 4096;
#pragma unroll
            for (int k8 = 0; k8 < 4; k8++) {
                uint32_t a[4][4];
#pragma unroll
                for (int mf = 0; mf < 4; mf++) {
                    float4 v = *(const float4*)(SA + (((mw0 + mf) * 4 + k8) * 32 + lane) * 4);
                    a[mf][0] = __float_as_uint(v.x);
                    a[mf][1] = __float_as_uint(v.y);
                    a[mf][2] = __float_as_uint(v.z);
                    a[mf][3] = __float_as_uint(v.w);
                }
                uint32_t b0[4], b1[4];
#pragma unroll
                for (int nf = 0; nf < 4; nf++) {
                    b0[nf] = __float_as_uint(SB[((n80 + nf) * 4 + k8) * 32 + lane]);
                    b1[nf] = __float_as_uint(SB[2048 + ((n80 + nf) * 4 + k8) * 32 + lane]);
                }
#pragma unroll
                for (int mf = 0; mf < 4; mf++)
#pragma unroll
                    for (int nf = 0; nf < 4; nf++)
                        mma_tf32(acc[mf][nf], a[mf], b0[nf], b1[nf]);
            }
        }
        // ---- store prefetched regs into the other buffer
        if (step < 44) {
            float* S = smem + (buf ^ 1) * 8192;
#pragma unroll
            for (int j = 0; j < 4; j++) *(float4*)(S + (t + j * 256) * 4) = pa[j];
            float* SB = S + 4096;
            int k8 = kq >> 1, rp = kq & 1;
#pragma unroll
            for (int j = 0; j < 4; j++) {
                int px = px0 + 32 * j;
                int n8 = px >> 3, gg = px & 7;
                *(float4*)(SB + rp * 2048 + ((n8 * 4 + k8) * 32 + gg * 4)) = pb[j];
            }
        }
        __syncthreads();
    }

    // ---- epilogue: bias + scale, write to g_OUT
    float scale = (octile == 0) ? 0.25f : 1.0f;
#pragma unroll
    for (int mf = 0; mf < 4; mf++) {
        int oc = octile * 128 + (mw0 + mf) * 16 + g;
        float b0v = g_WB[oc];
        float b1v = g_WB[oc + 8];
        float* r0 = g_OUT + (size_t)(b * 640 + oc) * HW + y0 * WW;
        float* r1 = r0 + (size_t)8 * HW;
#pragma unroll
        for (int nf = 0; nf < 4; nf++) {
            int n = (n80 + nf) * 8 + tt * 2;
            float2 o0, o1;
            o0.x = (acc[mf][nf][0] + b0v) * scale;
            o0.y = (acc[mf][nf][1] + b0v) * scale;
            o1.x = (acc[mf][nf][2] + b1v) * scale;
            o1.y = (acc[mf][nf][3] + b1v) * scale;
            *(float2*)(r0 + n) = o0;
            *(float2*)(r1 + n) = o1;
        }
    }
}

// ---------------------------------------------------------------------------
// Fused depthwise conv + logits + softmax + V   (proven R0 version)
// ---------------------------------------------------------------------------
__global__ __launch_bounds__(256) void attn_kernel(const float* __restrict__ dep_w,
                                                   const float* __restrict__ dep_b)
{
    __shared__ float s_raw[16][18 * 20];
    __shared__ float s_dw[144][9];
    __shared__ float s_db[144];

    int b    = blockIdx.z;
    int sn   = blockIdx.y;
    int sidx = sn >> 3;
    int n    = sn & 7;
    int ty0  = (blockIdx.x >> 3) * 16;
    int tx0  = (blockIdx.x & 7) * 16;
    int t    = threadIdx.x;
    int ly   = t >> 4, lx = t & 15;
    int Y    = ty0 + ly, X = tx0 + lx;

    for (int i = t; i < 144 * 9; i += 256) s_dw[i / 9][i % 9] = dep_w[i];
    if (t < 144) s_db[t] = dep_b[t];

    int kbase = (sidx == 0 ? 128 : 384) + n * 16;
    int vbase = (sidx == 0 ? 256 : 512) + n * 16;
    const float* Ob = g_OUT + (size_t)b * 640 * HW;

    for (int i = t; i < 16 * 324; i += 256) {
        int d  = i / 324;
        int r  = i % 324;
        int iy = r / 18, ix = r % 18;
        int yy = ty0 - 1 + iy, xx = tx0 - 1 + ix;
        float v = 0.0f;
        if (yy >= 0 && yy < HH && xx >= 0 && xx < WW)
            v = Ob[(size_t)(kbase + d) * HW + yy * WW + xx];
        s_raw[d][iy * 20 + ix] = v;
    }
    __syncthreads();

    float logit[9];
#pragma unroll
    for (int a = 0; a < 9; a++) logit[a] = 0.0f;

#pragma unroll 4
    for (int d = 0; d < 16; d++) {
        float qd = Ob[(size_t)(n * 16 + d) * HW + Y * WW + X];
        float tap[9];
#pragma unroll
        for (int ky = 0; ky < 3; ky++)
#pragma unroll
            for (int kx = 0; kx < 3; kx++)
                tap[ky * 3 + kx] = s_raw[d][(ly + ky) * 20 + lx + kx];
#pragma unroll
        for (int a = 0; a < 9; a++) {
            float kda = s_db[d * 9 + a];
#pragma unroll
            for (int k = 0; k < 9; k++) kda += s_dw[d * 9 + a][k] * tap[k];
            logit[a] += qd * kda;
        }
    }

    float m = logit[0];
#pragma unroll
    for (int a = 1; a < 9; a++) m = fmaxf(m, logit[a]);
    float attn[9];
    float sum = 0.0f;
#pragma unroll
    for (int a = 0; a < 9; a++) { attn[a] = __expf(logit[a] - m); sum += attn[a]; }
    float inv = 1.0f / sum;
#pragma unroll
    for (int a = 0; a < 9; a++) attn[a] *= inv;

    __syncthreads();
    for (int i = t; i < 16 * 324; i += 256) {
        int d  = i / 324;
        int r  = i % 324;
        int iy = r / 18, ix = r % 18;
        int yy = ty0 - 1 + iy, xx = tx0 - 1 + ix;
        float v = 0.0f;
        if (yy >= 0 && yy < HH && xx >= 0 && xx < WW)
            v = Ob[(size_t)(vbase + d) * HW + yy * WW + xx];
        s_raw[d][iy * 20 + ix] = v;
    }
    __syncthreads();

    float* outp = g_ATT + ((size_t)(b * 2 + sidx) * DIM + n * 16) * HW + Y * WW + X;
#pragma unroll 4
    for (int d = 0; d < 16; d++) {
        float tap[9];
#pragma unroll
        for (int ky = 0; ky < 3; ky++)
#pragma unroll
            for (int kx = 0; kx < 3; kx++)
                tap[ky * 3 + kx] = s_raw[d][(ly + ky) * 20 + lx + kx];
        float outd = 0.0f;
#pragma unroll
        for (int a = 0; a < 9; a++) {
            float vda = s_db[d * 9 + a];
#pragma unroll
            for (int k = 0; k < 9; k++) vda += s_dw[d * 9 + a][k] * tap[k];
            outd += attn[a] * vda;
        }
        outp[(size_t)d * HW] = outd;
    }
}

// ---------------------------------------------------------------------------
// 1x1 projection (proven R0 version)
// ---------------------------------------------------------------------------
__global__ __launch_bounds__(256) void proj_kernel(const float* __restrict__ wt,
                                                   const float* __restrict__ bias,
                                                   int sidx, float* __restrict__ out)
{
    __shared__ float s_w[32][128];
    __shared__ float s_in[32][64];

    int b  = blockIdx.y;
    int p0 = blockIdx.x * 64;
    int t  = threadIdx.x;
    int pg = t & 31;
    int og = t >> 5;

    float acc0[16], acc1[16];
#pragma unroll
    for (int o = 0; o < 16; o++) { acc0[o] = 0.0f; acc1[o] = 0.0f; }

    const float* inb = g_ATT + (size_t)(b * 2 + sidx) * DIM * HW;

    for (int c0 = 0; c0 < 128; c0 += 32) {
        for (int i = t; i < 32 * 128; i += 256) {
            int cc = i >> 7;
            int oc = i & 127;
            s_w[cc][oc] = wt[oc * 128 + c0 + cc];
        }
        for (int i = t; i < 32 * 64; i += 256) {
            int cc = i >> 6;
            int pp = i & 63;
            s_in[cc][pp] = inb[(size_t)(c0 + cc) * HW + p0 + pp];
        }
        __syncthreads();
#pragma unroll
        for (int cc = 0; cc < 32; cc++) {
            float i0 = s_in[cc][pg * 2];
            float i1 = s_in[cc][pg * 2 + 1];
#pragma unroll
            for (int o = 0; o < 16; o++) {
                float wv = s_w[cc][og * 16 + o];
                acc0[o] += i0 * wv;
                acc1[o] += i1 * wv;
            }
        }
        __syncthreads();
    }
#pragma unroll
    for (int o = 0; o < 16; o++) {
        int oc = og * 16 + o;
        float bs = bias[oc];
        out[(size_t)(b * 128 + oc) * HW + p0 + pg * 2]     = acc0[o] + bs;
        out[(size_t)(b * 128 + oc) * HW + p0 + pg * 2 + 1] = acc1[o] + bs;
    }
}

// ---------------------------------------------------------------------------
extern "C" void kernel_launch(void* const* d_in, const int* in_sizes, int n_in,
                              void* d_out, int out_size)
{
    const float* x        = (const float*)d_in[0];
    const float* ms       = (const float*)d_in[1];
    const float* lpan     = (const float*)d_in[2];
    const float* pan      = (const float*)d_in[3];
    const float* s        = (const float*)d_in[4];
    const float* q_w      = (const float*)d_in[5];
    const float* q_b      = (const float*)d_in[6];
    const float* k_pan_w  = (const float*)d_in[7];
    const float* k_pan_b  = (const float*)d_in[8];
    const float* v_pan_w  = (const float*)d_in[9];
    const float* v_pan_b  = (const float*)d_in[10];
    const float* kv_ms_w  = (const float*)d_in[11];
    const float* kv_ms_b  = (const float*)d_in[12];
    const float* dep_w    = (const float*)d_in[13];
    const float* dep_b    = (const float*)d_in[14];
    const float* ppan_w   = (const float*)d_in[15];
    const float* ppan_b   = (const float*)d_in[16];
    const float* pms_w    = (const float*)d_in[17];
    const float* pms_b    = (const float*)d_in[18];
    float* out = (float*)d_out;

    cudaFuncSetAttribute(conv_mma_kernel,
                         cudaFuncAttributeMaxDynamicSharedMemorySize, CONV_SMEM);

    dim3 xg(HW / 64, BB);
    build_xt_kernel<<<xg, 256>>>(x, ms, lpan, pan, s);
    zero_border_kernel<<<(BB * NPIX + 255) / 256, 256>>>();
    repack_w_kernel<<<(5 * 45 * 4096 + 255) / 256, 256>>>(
        q_w, k_pan_w, v_pan_w, kv_ms_w, q_b, k_pan_b, v_pan_b, kv_ms_b);

    dim3 cg(HH, 5, BB);
    conv_mma_kernel<<<cg, 256, CONV_SMEM>>>();

    dim3 ag(64, 16, BB);
    attn_kernel<<<ag, 256>>>(dep_w, dep_b);

    dim3 pg(HW / 64, BB);
    proj_kernel<<<pg, 256>>>(ppan_w, ppan_b, 0, out);
    proj_kernel<<<pg, 256>>>(pms_w,  pms_b,  1, out + (size_t)BB * DIM * HW);
}

// round 5
// speedup vs baseline: 4.7697x; 1.5245x over previous
#include <cuda_runtime.h>
#include <cuda_fp16.h>
#include <cstdint>
#include <math.h>

#define BB 2
#define HH 128
#define WW 128
#define HW (HH*WW)
#define DIM 128
#define NH 8
#define HD 16

#define CPAD 160            // unified channel count (147 used, padded)
#define PW 130              // padded image width/height
#define NPIX (PW*PW)

// ---------------- device scratch (allocation-free rule) ----------------
__device__ __align__(16) __half g_XTh[BB * NPIX * CPAD];  // padded fp16 activations [pix][ch-permuted]
__device__ __align__(16) __half g_WUh[5 * 45 * 4096];     // fragment-ordered fp16 weights
__device__ float g_WB[640];                                // biases
__device__ float g_OUT[BB * 640 * HW];                     // q | k_pan | v_pan | k_ms | v_ms
__device__ float g_ATT[BB * 2 * DIM * HW];                 // attention output

// ---------------- helpers ----------------
__device__ __forceinline__ void cp16(uint32_t dst, const void* src) {
    size_t gp;
    asm("cvta.to.global.u64 %0, %1;" : "=l"(gp) : "l"(src));
    asm volatile("cp.async.ca.shared.global [%0], [%1], 16;" :: "r"(dst), "l"(gp));
}

__device__ __forceinline__ void mma_f16(float* c, const uint32_t* a,
                                        uint32_t b0, uint32_t b1) {
    asm volatile(
        "mma.sync.aligned.m16n8k16.row.col.f32.f16.f16.f32 "
        "{%0,%1,%2,%3}, {%4,%5,%6,%7}, {%8,%9}, {%0,%1,%2,%3};"
        : "+f"(c[0]), "+f"(c[1]), "+f"(c[2]), "+f"(c[3])
        : "r"(a[0]), "r"(a[1]), "r"(a[2]), "r"(a[3]), "r"(b0), "r"(b1));
}

// ---------------------------------------------------------------------------
// build_xt: transpose x + derived channels into padded [pix][ch] fp16 layout.
// Channel order inside each 16-block is permuted to fragment order:
//   group p (p=0..3) holds channels {2p, 2p+1, 2p+8, 2p+9}
// ---------------------------------------------------------------------------
__global__ __launch_bounds__(256) void build_xt_kernel(
    const float* __restrict__ x, const float* __restrict__ ms,
    const float* __restrict__ lpan, const float* __restrict__ pan,
    const float* __restrict__ s)
{
    __shared__ float st[CPAD][65];
    int b  = blockIdx.y;
    int p0 = blockIdx.x * 64;
    int t  = threadIdx.x;
    float sv = s[b];

    for (int i = t; i < CPAD * 64; i += 256) {
        int c = i >> 6, px = i & 63;
        int p = p0 + px;
        float v = 0.0f;
        if (c < 128)        v = x[(b * 128 + c) * HW + p];
        else if (c < 136) { float lp = lpan[b * HW + p];
                            float m  = ms[(b * 8 + (c - 128)) * HW + p];
                            v = lp * (1.0f - sv) + m * sv; }
        else if (c == 136)  v = lpan[b * HW + p];
        else if (c == 137)  v = pan[b * HW + p];
        else if (c == 138)  v = pan[b * HW + p] - lpan[b * HW + p];
        else if (c < 147)   v = ms[(b * 8 + (c - 139)) * HW + p];
        st[c][px] = v;
    }
    __syncthreads();
    for (int i = t; i < 64 * 10; i += 256) {
        int px = i / 10, blk = i % 10;
        int p = p0 + px;
        int y = p >> 7, xx = p & 127;
        size_t pidx = (size_t)(y + 1) * PW + (xx + 1);
        __half h[16];
#pragma unroll
        for (int j = 0; j < 16; j++) {
            int pg2 = j >> 2, jj = j & 3;
            int ch = blk * 16 + pg2 * 2 + (jj & 1) + (jj >> 1) * 8;
            h[j] = __float2half(st[ch][px]);
        }
        __half* dst = g_XTh + ((size_t)b * NPIX + pidx) * CPAD + blk * 16;
        *(uint4*)dst       = *(uint4*)h;
        *(uint4*)(dst + 8) = *(uint4*)(h + 8);
    }
}

__global__ void zero_border_kernel()
{
    int idx = blockIdx.x * blockDim.x + threadIdx.x;
    if (idx >= BB * NPIX) return;
    int b = idx / NPIX, p = idx % NPIX;
    int py = p / PW, px = p % PW;
    if (py == 0 || py == PW - 1 || px == 0 || px == PW - 1) {
        uint4 z = {0u, 0u, 0u, 0u};
        uint4* dst = (uint4*)(g_XTh + ((size_t)b * NPIX + p) * CPAD);
#pragma unroll
        for (int i = 0; i < CPAD / 8; i++) dst[i] = z;
    }
}

// ---------------------------------------------------------------------------
// repack weights into m16n8k16 fragment order (fp16):
// g_WUh[octile][step=tap*5+kc][k16(2)][mfrag(8)][lane(32)][r(4)][e(2)]
//   m_local = mfrag*16 + lane/4 + (r&1)*8
//   k16loc  = (lane%4)*2 + e + (r>>1)*8
//   c       = (step%5)*32 + k16*16 + k16loc ; tap = step/5
// ---------------------------------------------------------------------------
__global__ void repack_w_kernel(
    const float* __restrict__ qw, const float* __restrict__ kpw,
    const float* __restrict__ vpw, const float* __restrict__ kvw,
    const float* __restrict__ qb, const float* __restrict__ kpb,
    const float* __restrict__ vpb, const float* __restrict__ kvb)
{
    int idx = blockIdx.x * blockDim.x + threadIdx.x;
    if (idx < 640) {
        float bv;
        if (idx < 128)      bv = qb[idx];
        else if (idx < 256) bv = kpb[idx - 128];
        else if (idx < 384) bv = vpb[idx - 256];
        else                bv = kvb[idx - 384];
        g_WB[idx] = bv;
    }
    if (idx >= 5 * 45 * 4096) return;
    int i2 = idx;
    int e     = i2 & 1;  i2 >>= 1;
    int r     = i2 & 3;  i2 >>= 2;
    int lane  = i2 & 31; i2 >>= 5;
    int mfrag = i2 & 7;  i2 >>= 3;
    int k16   = i2 & 1;  i2 >>= 1;
    int step  = i2 % 45;
    int octile = i2 / 45;

    int m_local = mfrag * 16 + (lane >> 2) + (r & 1) * 8;
    int c       = (step % 5) * 32 + k16 * 16 + (lane & 3) * 2 + e + (r >> 1) * 8;
    int tap     = step / 5;
    int oc_g    = octile * 128 + m_local;

    float v = 0.0f;
    if (oc_g < 128) {                               // q : x + cond(128-135)
        if (c < 136) v = qw[(oc_g * 136 + c) * 9 + tap];
    } else if (oc_g < 256) {                        // k_pan : x + lpan(136)
        int oc = oc_g - 128;
        if (c < 128)       v = kpw[(oc * 129 + c) * 9 + tap];
        else if (c == 136) v = kpw[(oc * 129 + 128) * 9 + tap];
    } else if (oc_g < 384) {                        // v_pan : x + 136,137,138
        int oc = oc_g - 256;
        if (c < 128)                  v = vpw[(oc * 131 + c) * 9 + tap];
        else if (c >= 136 && c < 139) v = vpw[(oc * 131 + 128 + (c - 136)) * 9 + tap];
    } else {                                        // kv_ms : x + ms(139-146)
        int oc = oc_g - 384;
        if (c < 128)                  v = kvw[(oc * 136 + c) * 9 + tap];
        else if (c >= 139 && c < 147) v = kvw[(oc * 136 + 128 + (c - 139)) * 9 + tap];
    }
    g_WUh[idx] = __float2half(v);
}

// ---------------------------------------------------------------------------
// conv via mma.sync m16n8k16 fp16. CTA: 128 oc x 128 px (one image row).
// 8 warps = 2(m) x 4(n); warp tile 64 oc x 32 px.
// 45 K-steps of K=32 (9 taps x 5 channel chunks), cp.async double buffer.
// smem per stage: A 8KB | B 8KB.
// ---------------------------------------------------------------------------
#define CONV_SMEM (2 * 16384)
__global__ __launch_bounds__(256) void conv_mma_kernel()
{
    extern __shared__ char smem[];
    int t = threadIdx.x;
    int w = t >> 5, lane = t & 31;
    int g = lane >> 2, tt = lane & 3;
    int y0 = blockIdx.x;
    int octile = blockIdx.y;
    int b = blockIdx.z;

    int mw0 = (w >> 2) * 4;   // warp's mfrag base (0 or 4)
    int n80 = (w & 3) * 4;    // warp's n8 base

    const __half* XTb = g_XTh + (size_t)b * NPIX * CPAD;
    const __half* WUo = g_WUh + (size_t)octile * 45 * 4096;
    uint32_t sbase = (uint32_t)__cvta_generic_to_shared(smem);

    int pxl = t >> 1, k16s = t & 1;   // loader roles

    float acc[4][4][4];
#pragma unroll
    for (int mf = 0; mf < 4; mf++)
#pragma unroll
        for (int nf = 0; nf < 4; nf++)
#pragma unroll
            for (int r = 0; r < 4; r++) acc[mf][nf][r] = 0.0f;

    auto issue = [&](int step, int stage) {
        uint32_t sA = sbase + stage * 16384;
        uint32_t sB = sA + 8192;
        const char* Ws = (const char*)(WUo + (size_t)step * 4096);
        cp16(sA + t * 32,      Ws + t * 32);
        cp16(sA + t * 32 + 16, Ws + t * 32 + 16);
        int tap = step / 5, kc = (step % 5) * 32;
        int dy = tap / 3 - 1, dx = tap % 3 - 1;
        const char* src = (const char*)(XTb +
            ((size_t)(y0 + dy + 1) * PW + (pxl + dx + 1)) * CPAD + kc + k16s * 16);
        uint32_t d = sB + k16s * 4096 + pxl * 32;
        cp16(d,      src);
        cp16(d + 16, src + 16);
        asm volatile("cp.async.commit_group;" ::: "memory");
    };

    issue(0, 0);
    for (int step = 0; step < 45; step++) {
        int stage = step & 1;
        if (step + 1 < 45) {
            issue(step + 1, stage ^ 1);
            asm volatile("cp.async.wait_group 1;" ::: "memory");
        } else {
            asm volatile("cp.async.wait_group 0;" ::: "memory");
        }
        __syncthreads();

        uint32_t sA = sbase + stage * 16384;
        uint32_t sB = sA + 8192;
#pragma unroll
        for (int k16 = 0; k16 < 2; k16++) {
            uint32_t a[4][4];
#pragma unroll
            for (int mf = 0; mf < 4; mf++) {
                uint32_t addr = sA + k16 * 4096 + (mw0 + mf) * 512 + lane * 16;
                asm volatile("ld.shared.v4.u32 {%0,%1,%2,%3}, [%4];"
                    : "=r"(a[mf][0]), "=r"(a[mf][1]), "=r"(a[mf][2]), "=r"(a[mf][3])
                    : "r"(addr));
            }
            uint32_t b0[4], b1[4];
#pragma unroll
            for (int nf = 0; nf < 4; nf++) {
                uint32_t addr = sB + k16 * 4096 +
                                (((n80 + nf) * 8 + g) * 32) + tt * 8;
                asm volatile("ld.shared.v2.u32 {%0,%1}, [%2];"
                    : "=r"(b0[nf]), "=r"(b1[nf]) : "r"(addr));
            }
#pragma unroll
            for (int mf = 0; mf < 4; mf++)
#pragma unroll
                for (int nf = 0; nf < 4; nf++)
                    mma_f16(acc[mf][nf], a[mf], b0[nf], b1[nf]);
        }
        __syncthreads();
    }

    // ---- epilogue: bias + scale, write to g_OUT
    float scale = (octile == 0) ? 0.25f : 1.0f;
#pragma unroll
    for (int mf = 0; mf < 4; mf++) {
        int oc = octile * 128 + (mw0 + mf) * 16 + g;
        float b0v = g_WB[oc];
        float b1v = g_WB[oc + 8];
        float* r0 = g_OUT + (size_t)(b * 640 + oc) * HW + y0 * WW;
        float* r1 = r0 + (size_t)8 * HW;
#pragma unroll
        for (int nf = 0; nf < 4; nf++) {
            int n = (n80 + nf) * 8 + tt * 2;
            float2 o0, o1;
            o0.x = (acc[mf][nf][0] + b0v) * scale;
            o0.y = (acc[mf][nf][1] + b0v) * scale;
            o1.x = (acc[mf][nf][2] + b1v) * scale;
            o1.y = (acc[mf][nf][3] + b1v) * scale;
            *(float2*)(r0 + n) = o0;
            *(float2*)(r1 + n) = o1;
        }
    }
}

// ---------------------------------------------------------------------------
// Fused depthwise conv + logits + softmax + V   (proven version)
// ---------------------------------------------------------------------------
__global__ __launch_bounds__(256) void attn_kernel(const float* __restrict__ dep_w,
                                                   const float* __restrict__ dep_b)
{
    __shared__ float s_raw[16][18 * 20];
    __shared__ float s_dw[144][9];
    __shared__ float s_db[144];

    int b    = blockIdx.z;
    int sn   = blockIdx.y;
    int sidx = sn >> 3;
    int n    = sn & 7;
    int ty0  = (blockIdx.x >> 3) * 16;
    int tx0  = (blockIdx.x & 7) * 16;
    int t    = threadIdx.x;
    int ly   = t >> 4, lx = t & 15;
    int Y    = ty0 + ly, X = tx0 + lx;

    for (int i = t; i < 144 * 9; i += 256) s_dw[i / 9][i % 9] = dep_w[i];
    if (t < 144) s_db[t] = dep_b[t];

    int kbase = (sidx == 0 ? 128 : 384) + n * 16;
    int vbase = (sidx == 0 ? 256 : 512) + n * 16;
    const float* Ob = g_OUT + (size_t)b * 640 * HW;

    for (int i = t; i < 16 * 324; i += 256) {
        int d  = i / 324;
        int r  = i % 324;
        int iy = r / 18, ix = r % 18;
        int yy = ty0 - 1 + iy, xx = tx0 - 1 + ix;
        float v = 0.0f;
        if (yy >= 0 && yy < HH && xx >= 0 && xx < WW)
            v = Ob[(size_t)(kbase + d) * HW + yy * WW + xx];
        s_raw[d][iy * 20 + ix] = v;
    }
    __syncthreads();

    float logit[9];
#pragma unroll
    for (int a = 0; a < 9; a++) logit[a] = 0.0f;

#pragma unroll 4
    for (int d = 0; d < 16; d++) {
        float qd = Ob[(size_t)(n * 16 + d) * HW + Y * WW + X];
        float tap[9];
#pragma unroll
        for (int ky = 0; ky < 3; ky++)
#pragma unroll
            for (int kx = 0; kx < 3; kx++)
                tap[ky * 3 + kx] = s_raw[d][(ly + ky) * 20 + lx + kx];
#pragma unroll
        for (int a = 0; a < 9; a++) {
            float kda = s_db[d * 9 + a];
#pragma unroll
            for (int k = 0; k < 9; k++) kda += s_dw[d * 9 + a][k] * tap[k];
            logit[a] += qd * kda;
        }
    }

    float m = logit[0];
#pragma unroll
    for (int a = 1; a < 9; a++) m = fmaxf(m, logit[a]);
    float attn[9];
    float sum = 0.0f;
#pragma unroll
    for (int a = 0; a < 9; a++) { attn[a] = __expf(logit[a] - m); sum += attn[a]; }
    float inv = 1.0f / sum;
#pragma unroll
    for (int a = 0; a < 9; a++) attn[a] *= inv;

    __syncthreads();
    for (int i = t; i < 16 * 324; i += 256) {
        int d  = i / 324;
        int r  = i % 324;
        int iy = r / 18, ix = r % 18;
        int yy = ty0 - 1 + iy, xx = tx0 - 1 + ix;
        float v = 0.0f;
        if (yy >= 0 && yy < HH && xx >= 0 && xx < WW)
            v = Ob[(size_t)(vbase + d) * HW + yy * WW + xx];
        s_raw[d][iy * 20 + ix] = v;
    }
    __syncthreads();

    float* outp = g_ATT + ((size_t)(b * 2 + sidx) * DIM + n * 16) * HW + Y * WW + X;
#pragma unroll 4
    for (int d = 0; d < 16; d++) {
        float tap[9];
#pragma unroll
        for (int ky = 0; ky < 3; ky++)
#pragma unroll
            for (int kx = 0; kx < 3; kx++)
                tap[ky * 3 + kx] = s_raw[d][(ly + ky) * 20 + lx + kx];
        float outd = 0.0f;
#pragma unroll
        for (int a = 0; a < 9; a++) {
            float vda = s_db[d * 9 + a];
#pragma unroll
            for (int k = 0; k < 9; k++) vda += s_dw[d * 9 + a][k] * tap[k];
            outd += attn[a] * vda;
        }
        outp[(size_t)d * HW] = outd;
    }
}

// ---------------------------------------------------------------------------
// 1x1 projection (proven version)
// ---------------------------------------------------------------------------
__global__ __launch_bounds__(256) void proj_kernel(const float* __restrict__ wt,
                                                   const float* __restrict__ bias,
                                                   int sidx, float* __restrict__ out)
{
    __shared__ float s_w[32][128];
    __shared__ float s_in[32][64];

    int b  = blockIdx.y;
    int p0 = blockIdx.x * 64;
    int t  = threadIdx.x;
    int pg = t & 31;
    int og = t >> 5;

    float acc0[16], acc1[16];
#pragma unroll
    for (int o = 0; o < 16; o++) { acc0[o] = 0.0f; acc1[o] = 0.0f; }

    const float* inb = g_ATT + (size_t)(b * 2 + sidx) * DIM * HW;

    for (int c0 = 0; c0 < 128; c0 += 32) {
        for (int i = t; i < 32 * 128; i += 256) {
            int cc = i >> 7;
            int oc = i & 127;
            s_w[cc][oc] = wt[oc * 128 + c0 + cc];
        }
        for (int i = t; i < 32 * 64; i += 256) {
            int cc = i >> 6;
            int pp = i & 63;
            s_in[cc][pp] = inb[(size_t)(c0 + cc) * HW + p0 + pp];
        }
        __syncthreads();
#pragma unroll
        for (int cc = 0; cc < 32; cc++) {
            float i0 = s_in[cc][pg * 2];
            float i1 = s_in[cc][pg * 2 + 1];
#pragma unroll
            for (int o = 0; o < 16; o++) {
                float wv = s_w[cc][og * 16 + o];
                acc0[o] += i0 * wv;
                acc1[o] += i1 * wv;
            }
        }
        __syncthreads();
    }
#pragma unroll
    for (int o = 0; o < 16; o++) {
        int oc = og * 16 + o;
        float bs = bias[oc];
        out[(size_t)(b * 128 + oc) * HW + p0 + pg * 2]     = acc0[o] + bs;
        out[(size_t)(b * 128 + oc) * HW + p0 + pg * 2 + 1] = acc1[o] + bs;
    }
}

// ---------------------------------------------------------------------------
extern "C" void kernel_launch(void* const* d_in, const int* in_sizes, int n_in,
                              void* d_out, int out_size)
{
    const float* x        = (const float*)d_in[0];
    const float* ms       = (const float*)d_in[1];
    const float* lpan     = (const float*)d_in[2];
    const float* pan      = (const float*)d_in[3];
    const float* s        = (const float*)d_in[4];
    const float* q_w      = (const float*)d_in[5];
    const float* q_b      = (const float*)d_in[6];
    const float* k_pan_w  = (const float*)d_in[7];
    const float* k_pan_b  = (const float*)d_in[8];
    const float* v_pan_w  = (const float*)d_in[9];
    const float* v_pan_b  = (const float*)d_in[10];
    const float* kv_ms_w  = (const float*)d_in[11];
    const float* kv_ms_b  = (const float*)d_in[12];
    const float* dep_w    = (const float*)d_in[13];
    const float* dep_b    = (const float*)d_in[14];
    const float* ppan_w   = (const float*)d_in[15];
    const float* ppan_b   = (const float*)d_in[16];
    const float* pms_w    = (const float*)d_in[17];
    const float* pms_b    = (const float*)d_in[18];
    float* out = (float*)d_out;

    cudaFuncSetAttribute(conv_mma_kernel,
                         cudaFuncAttributeMaxDynamicSharedMemorySize, CONV_SMEM);

    dim3 xg(HW / 64, BB);
    build_xt_kernel<<<xg, 256>>>(x, ms, lpan, pan, s);
    zero_border_kernel<<<(BB * NPIX + 255) / 256, 256>>>();
    repack_w_kernel<<<(5 * 45 * 4096 + 255) / 256, 256>>>(
        q_w, k_pan_w, v_pan_w, kv_ms_w, q_b, k_pan_b, v_pan_b, kv_ms_b);

    dim3 cg(HH, 5, BB);
    conv_mma_kernel<<<cg, 256, CONV_SMEM>>>();

    dim3 ag(64, 16, BB);
    attn_kernel<<<ag, 256>>>(dep_w, dep_b);

    dim3 pg(HW / 64, BB);
    proj_kernel<<<pg, 256>>>(ppan_w, ppan_b, 0, out);
    proj_kernel<<<pg, 256>>>(pms_w,  pms_b,  1, out + (size_t)BB * DIM * HW);
}

// round 6
// speedup vs baseline: 5.5341x; 1.1603x over previous
#include <cuda_runtime.h>
#include <cuda_fp16.h>
#include <cstdint>
#include <math.h>

#define BB 2
#define HH 128
#define WW 128
#define HW (HH*WW)
#define DIM 128
#define NH 8
#define HD 16

#define CPAD 160            // unified channel count (147 used, padded)
#define PW 130              // padded image width/height
#define NPIX (PW*PW)

// ---------------- device scratch (allocation-free rule) ----------------
__device__ __align__(16) __half g_XTh[BB * NPIX * CPAD];  // padded fp16 activations [pix][ch-permuted]
__device__ __align__(16) __half g_WUh[5 * 45 * 4096];     // fragment-ordered fp16 conv weights
__device__ __align__(16) __half g_WPh[2 * 16384];         // fragment-ordered fp16 proj weights
__device__ __align__(16) __half g_ATTh[BB * 2 * HW * 128];// attn out, [b,s][pix][ch-permuted] fp16
__device__ float g_WB[640];                                // conv biases
__device__ float g_OUT[BB * 640 * HW];                     // q | k_pan | v_pan | k_ms | v_ms

// ---------------- helpers ----------------
__device__ __forceinline__ void cp16(uint32_t dst, const void* src) {
    size_t gp;
    asm("cvta.to.global.u64 %0, %1;" : "=l"(gp) : "l"(src));
    asm volatile("cp.async.ca.shared.global [%0], [%1], 16;" :: "r"(dst), "l"(gp));
}

__device__ __forceinline__ void mma_f16(float* c, const uint32_t* a,
                                        uint32_t b0, uint32_t b1) {
    asm volatile(
        "mma.sync.aligned.m16n8k16.row.col.f32.f16.f16.f32 "
        "{%0,%1,%2,%3}, {%4,%5,%6,%7}, {%8,%9}, {%0,%1,%2,%3};"
        : "+f"(c[0]), "+f"(c[1]), "+f"(c[2]), "+f"(c[3])
        : "r"(a[0]), "r"(a[1]), "r"(a[2]), "r"(a[3]), "r"(b0), "r"(b1));
}

// ---------------------------------------------------------------------------
// build_xt: transpose x + derived channels into padded [pix][ch] fp16 layout.
// Channel order inside each 16-block is permuted to fragment order:
//   group p (p=0..3) holds channels {2p, 2p+1, 2p+8, 2p+9}
// ---------------------------------------------------------------------------
__global__ __launch_bounds__(256) void build_xt_kernel(
    const float* __restrict__ x, const float* __restrict__ ms,
    const float* __restrict__ lpan, const float* __restrict__ pan,
    const float* __restrict__ s)
{
    __shared__ float st[CPAD][65];
    int b  = blockIdx.y;
    int p0 = blockIdx.x * 64;
    int t  = threadIdx.x;
    float sv = s[b];

    for (int i = t; i < CPAD * 64; i += 256) {
        int c = i >> 6, px = i & 63;
        int p = p0 + px;
        float v = 0.0f;
        if (c < 128)        v = x[(b * 128 + c) * HW + p];
        else if (c < 136) { float lp = lpan[b * HW + p];
                            float m  = ms[(b * 8 + (c - 128)) * HW + p];
                            v = lp * (1.0f - sv) + m * sv; }
        else if (c == 136)  v = lpan[b * HW + p];
        else if (c == 137)  v = pan[b * HW + p];
        else if (c == 138)  v = pan[b * HW + p] - lpan[b * HW + p];
        else if (c < 147)   v = ms[(b * 8 + (c - 139)) * HW + p];
        st[c][px] = v;
    }
    __syncthreads();
    for (int i = t; i < 64 * 10; i += 256) {
        int px = i / 10, blk = i % 10;
        int p = p0 + px;
        int y = p >> 7, xx = p & 127;
        size_t pidx = (size_t)(y + 1) * PW + (xx + 1);
        __half h[16];
#pragma unroll
        for (int j = 0; j < 16; j++) {
            int pg2 = j >> 2, jj = j & 3;
            int ch = blk * 16 + pg2 * 2 + (jj & 1) + (jj >> 1) * 8;
            h[j] = __float2half(st[ch][px]);
        }
        __half* dst = g_XTh + ((size_t)b * NPIX + pidx) * CPAD + blk * 16;
        *(uint4*)dst       = *(uint4*)h;
        *(uint4*)(dst + 8) = *(uint4*)(h + 8);
    }
}

__global__ void zero_border_kernel()
{
    int idx = blockIdx.x * blockDim.x + threadIdx.x;
    if (idx >= BB * NPIX) return;
    int b = idx / NPIX, p = idx % NPIX;
    int py = p / PW, px = p % PW;
    if (py == 0 || py == PW - 1 || px == 0 || px == PW - 1) {
        uint4 z = {0u, 0u, 0u, 0u};
        uint4* dst = (uint4*)(g_XTh + ((size_t)b * NPIX + p) * CPAD);
#pragma unroll
        for (int i = 0; i < CPAD / 8; i++) dst[i] = z;
    }
}

// ---------------------------------------------------------------------------
// repack conv weights into m16n8k16 fragment order (fp16)
// ---------------------------------------------------------------------------
__global__ void repack_w_kernel(
    const float* __restrict__ qw, const float* __restrict__ kpw,
    const float* __restrict__ vpw, const float* __restrict__ kvw,
    const float* __restrict__ qb, const float* __restrict__ kpb,
    const float* __restrict__ vpb, const float* __restrict__ kvb)
{
    int idx = blockIdx.x * blockDim.x + threadIdx.x;
    if (idx < 640) {
        float bv;
        if (idx < 128)      bv = qb[idx];
        else if (idx < 256) bv = kpb[idx - 128];
        else if (idx < 384) bv = vpb[idx - 256];
        else                bv = kvb[idx - 384];
        g_WB[idx] = bv;
    }
    if (idx >= 5 * 45 * 4096) return;
    int i2 = idx;
    int e     = i2 & 1;  i2 >>= 1;
    int r     = i2 & 3;  i2 >>= 2;
    int lane  = i2 & 31; i2 >>= 5;
    int mfrag = i2 & 7;  i2 >>= 3;
    int k16   = i2 & 1;  i2 >>= 1;
    int step  = i2 % 45;
    int octile = i2 / 45;

    int m_local = mfrag * 16 + (lane >> 2) + (r & 1) * 8;
    int c       = (step % 5) * 32 + k16 * 16 + (lane & 3) * 2 + e + (r >> 1) * 8;
    int tap     = step / 5;
    int oc_g    = octile * 128 + m_local;

    float v = 0.0f;
    if (oc_g < 128) {
        if (c < 136) v = qw[(oc_g * 136 + c) * 9 + tap];
    } else if (oc_g < 256) {
        int oc = oc_g - 128;
        if (c < 128)       v = kpw[(oc * 129 + c) * 9 + tap];
        else if (c == 136) v = kpw[(oc * 129 + 128) * 9 + tap];
    } else if (oc_g < 384) {
        int oc = oc_g - 256;
        if (c < 128)                  v = vpw[(oc * 131 + c) * 9 + tap];
        else if (c >= 136 && c < 139) v = vpw[(oc * 131 + 128 + (c - 136)) * 9 + tap];
    } else {
        int oc = oc_g - 384;
        if (c < 128)                  v = kvw[(oc * 136 + c) * 9 + tap];
        else if (c >= 139 && c < 147) v = kvw[(oc * 136 + 128 + (c - 139)) * 9 + tap];
    }
    g_WUh[idx] = __float2half(v);
}

// ---------------------------------------------------------------------------
// repack proj weights (128x128 each) into same A-fragment order
// halves index: ((k16*8+mf)*32+lane)*8 + r*2 + e
// ---------------------------------------------------------------------------
__global__ void repack_proj_kernel(const float* __restrict__ pw,
                                   const float* __restrict__ mw)
{
    int idx = blockIdx.x * blockDim.x + threadIdx.x;
    if (idx >= 2 * 16384) return;
    int s  = idx >> 14;
    int i2 = idx & 16383;
    int e    = i2 & 1;
    int r    = (i2 >> 1) & 3;
    int lane = (i2 >> 3) & 31;
    int mf   = (i2 >> 8) & 7;
    int k16  = i2 >> 11;
    int m = mf * 16 + (lane >> 2) + (r & 1) * 8;
    int c = k16 * 16 + (lane & 3) * 2 + e + (r >> 1) * 8;
    const float* src = s ? mw : pw;
    g_WPh[idx] = __float2half(src[m * 128 + c]);
}

// ---------------------------------------------------------------------------
// conv via mma.sync m16n8k16 fp16 (unchanged from R5 — benched 244us)
// ---------------------------------------------------------------------------
#define CONV_SMEM (2 * 16384)
__global__ __launch_bounds__(256) void conv_mma_kernel()
{
    extern __shared__ char smem[];
    int t = threadIdx.x;
    int w = t >> 5, lane = t & 31;
    int g = lane >> 2, tt = lane & 3;
    int y0 = blockIdx.x;
    int octile = blockIdx.y;
    int b = blockIdx.z;

    int mw0 = (w >> 2) * 4;
    int n80 = (w & 3) * 4;

    const __half* XTb = g_XTh + (size_t)b * NPIX * CPAD;
    const __half* WUo = g_WUh + (size_t)octile * 45 * 4096;
    uint32_t sbase = (uint32_t)__cvta_generic_to_shared(smem);

    int pxl = t >> 1, k16s = t & 1;

    float acc[4][4][4];
#pragma unroll
    for (int mf = 0; mf < 4; mf++)
#pragma unroll
        for (int nf = 0; nf < 4; nf++)
#pragma unroll
            for (int r = 0; r < 4; r++) acc[mf][nf][r] = 0.0f;

    auto issue = [&](int step, int stage) {
        uint32_t sA = sbase + stage * 16384;
        uint32_t sB = sA + 8192;
        const char* Ws = (const char*)(WUo + (size_t)step * 4096);
        cp16(sA + t * 32,      Ws + t * 32);
        cp16(sA + t * 32 + 16, Ws + t * 32 + 16);
        int tap = step / 5, kc = (step % 5) * 32;
        int dy = tap / 3 - 1, dx = tap % 3 - 1;
        const char* src = (const char*)(XTb +
            ((size_t)(y0 + dy + 1) * PW + (pxl + dx + 1)) * CPAD + kc + k16s * 16);
        uint32_t d = sB + k16s * 4096 + pxl * 32;
        cp16(d,      src);
        cp16(d + 16, src + 16);
        asm volatile("cp.async.commit_group;" ::: "memory");
    };

    issue(0, 0);
    for (int step = 0; step < 45; step++) {
        int stage = step & 1;
        if (step + 1 < 45) {
            issue(step + 1, stage ^ 1);
            asm volatile("cp.async.wait_group 1;" ::: "memory");
        } else {
            asm volatile("cp.async.wait_group 0;" ::: "memory");
        }
        __syncthreads();

        uint32_t sA = sbase + stage * 16384;
        uint32_t sB = sA + 8192;
#pragma unroll
        for (int k16 = 0; k16 < 2; k16++) {
            uint32_t a[4][4];
#pragma unroll
            for (int mf = 0; mf < 4; mf++) {
                uint32_t addr = sA + k16 * 4096 + (mw0 + mf) * 512 + lane * 16;
                asm volatile("ld.shared.v4.u32 {%0,%1,%2,%3}, [%4];"
                    : "=r"(a[mf][0]), "=r"(a[mf][1]), "=r"(a[mf][2]), "=r"(a[mf][3])
                    : "r"(addr));
            }
            uint32_t b0[4], b1[4];
#pragma unroll
            for (int nf = 0; nf < 4; nf++) {
                uint32_t addr = sB + k16 * 4096 +
                                (((n80 + nf) * 8 + g) * 32) + tt * 8;
                asm volatile("ld.shared.v2.u32 {%0,%1}, [%2];"
                    : "=r"(b0[nf]), "=r"(b1[nf]) : "r"(addr));
            }
#pragma unroll
            for (int mf = 0; mf < 4; mf++)
#pragma unroll
                for (int nf = 0; nf < 4; nf++)
                    mma_f16(acc[mf][nf], a[mf], b0[nf], b1[nf]);
        }
        __syncthreads();
    }

    float scale = (octile == 0) ? 0.25f : 1.0f;
#pragma unroll
    for (int mf = 0; mf < 4; mf++) {
        int oc = octile * 128 + (mw0 + mf) * 16 + g;
        float b0v = g_WB[oc];
        float b1v = g_WB[oc + 8];
        float* r0 = g_OUT + (size_t)(b * 640 + oc) * HW + y0 * WW;
        float* r1 = r0 + (size_t)8 * HW;
#pragma unroll
        for (int nf = 0; nf < 4; nf++) {
            int n = (n80 + nf) * 8 + tt * 2;
            float2 o0, o1;
            o0.x = (acc[mf][nf][0] + b0v) * scale;
            o0.y = (acc[mf][nf][1] + b0v) * scale;
            o1.x = (acc[mf][nf][2] + b1v) * scale;
            o1.y = (acc[mf][nf][3] + b1v) * scale;
            *(float2*)(r0 + n) = o0;
            *(float2*)(r1 + n) = o1;
        }
    }
}

// ---------------------------------------------------------------------------
// attn v2: 32x32 tile, 256 threads, 2x2 px/thread, per-d smem staging.
// Output written fp16 in proj fragment layout (g_ATTh).
// ---------------------------------------------------------------------------
__global__ __launch_bounds__(256) void attn_kernel(const float* __restrict__ dep_w,
                                                   const float* __restrict__ dep_b)
{
    __shared__ float s_dw[144][9];
    __shared__ float s_db[144];
    __shared__ float s_tile[34][36];

    int b    = blockIdx.z;
    int sn   = blockIdx.y;
    int sidx = sn >> 3, n = sn & 7;
    int tY   = (blockIdx.x >> 2) * 32;
    int tX   = (blockIdx.x & 3) * 32;
    int t    = threadIdx.x;
    int ty   = t >> 4, tx = t & 15;
    int py0  = tY + 2 * ty, px0 = tX + 2 * tx;

    for (int i = t; i < 144 * 9; i += 256) s_dw[i / 9][i % 9] = dep_w[i];
    if (t < 144) s_db[t] = dep_b[t];

    int kbase = (sidx == 0 ? 128 : 384) + n * 16;
    int vbase = kbase + 128;
    const float* Ob = g_OUT + (size_t)b * 640 * HW;

    float logit[4][9];
#pragma unroll
    for (int p = 0; p < 4; p++)
#pragma unroll
        for (int a = 0; a < 9; a++) logit[p][a] = 0.0f;

    // ---- phase K: logits
    for (int d = 0; d < 16; d++) {
        __syncthreads();
        const float* P = Ob + (size_t)(kbase + d) * HW;
        for (int i = t; i < 34 * 34; i += 256) {
            int r = i / 34, c = i % 34;
            int yy = tY - 1 + r, xx = tX - 1 + c;
            float v = 0.0f;
            if (yy >= 0 && yy < HH && xx >= 0 && xx < WW) v = P[yy * WW + xx];
            s_tile[r][c] = v;
        }
        __syncthreads();
        float tap[4][4];
#pragma unroll
        for (int yy = 0; yy < 4; yy++)
#pragma unroll
            for (int xx = 0; xx < 4; xx++)
                tap[yy][xx] = s_tile[2 * ty + yy][2 * tx + xx];
        const float* Pq = Ob + (size_t)(n * 16 + d) * HW + py0 * WW + px0;
        float qv[4] = {Pq[0], Pq[1], Pq[WW], Pq[WW + 1]};
#pragma unroll
        for (int a = 0; a < 9; a++) {
            const float* wp = s_dw[d * 9 + a];
            float w9[9];
#pragma unroll
            for (int k = 0; k < 9; k++) w9[k] = wp[k];
            float bsv = s_db[d * 9 + a];
#pragma unroll
            for (int p = 0; p < 4; p++) {
                int oy = p >> 1, ox = p & 1;
                float kda = bsv;
#pragma unroll
                for (int ky = 0; ky < 3; ky++)
#pragma unroll
                    for (int kx = 0; kx < 3; kx++)
                        kda += w9[ky * 3 + kx] * tap[oy + ky][ox + kx];
                logit[p][a] += qv[p] * kda;
            }
        }
    }

    // ---- softmax
    float attnv[4][9];
#pragma unroll
    for (int p = 0; p < 4; p++) {
        float m = logit[p][0];
#pragma unroll
        for (int a = 1; a < 9; a++) m = fmaxf(m, logit[p][a]);
        float sum = 0.0f;
#pragma unroll
        for (int a = 0; a < 9; a++) { attnv[p][a] = __expf(logit[p][a] - m); sum += attnv[p][a]; }
        float inv = 1.0f / sum;
#pragma unroll
        for (int a = 0; a < 9; a++) attnv[p][a] *= inv;
    }

    // ---- phase V: weighted sum, accumulate fp16 output block in regs
    __half oh[4][16];
#pragma unroll
    for (int d = 0; d < 16; d++) {
        __syncthreads();
        const float* P = Ob + (size_t)(vbase + d) * HW;
        for (int i = t; i < 34 * 34; i += 256) {
            int r = i / 34, c = i % 34;
            int yy = tY - 1 + r, xx = tX - 1 + c;
            float v = 0.0f;
            if (yy >= 0 && yy < HH && xx >= 0 && xx < WW) v = P[yy * WW + xx];
            s_tile[r][c] = v;
        }
        __syncthreads();
        float tap[4][4];
#pragma unroll
        for (int yy = 0; yy < 4; yy++)
#pragma unroll
            for (int xx = 0; xx < 4; xx++)
                tap[yy][xx] = s_tile[2 * ty + yy][2 * tx + xx];
        float outv[4] = {0.f, 0.f, 0.f, 0.f};
#pragma unroll
        for (int a = 0; a < 9; a++) {
            const float* wp = s_dw[d * 9 + a];
            float w9[9];
#pragma unroll
            for (int k = 0; k < 9; k++) w9[k] = wp[k];
            float bsv = s_db[d * 9 + a];
#pragma unroll
            for (int p = 0; p < 4; p++) {
                int oy = p >> 1, ox = p & 1;
                float vda = bsv;
#pragma unroll
                for (int ky = 0; ky < 3; ky++)
#pragma unroll
                    for (int kx = 0; kx < 3; kx++)
                        vda += w9[ky * 3 + kx] * tap[oy + ky][ox + kx];
                outv[p] += attnv[p][a] * vda;
            }
        }
        // fragment-permuted slot for channel-local d
        const int h2 = d >> 3, rem = d & 7;
        const int j  = (rem >> 1) * 4 + h2 * 2 + (rem & 1);
#pragma unroll
        for (int p = 0; p < 4; p++) oh[p][j] = __float2half(outv[p]);
    }

    __half* Adst = g_ATTh + (size_t)(b * 2 + sidx) * HW * 128;
#pragma unroll
    for (int p = 0; p < 4; p++) {
        int pix = (py0 + (p >> 1)) * WW + px0 + (p & 1);
        __half* dst = Adst + (size_t)pix * 128 + n * 16;
        *(uint4*)dst       = *(uint4*)&oh[p][0];
        *(uint4*)(dst + 8) = *(uint4*)&oh[p][8];
    }
}

// ---------------------------------------------------------------------------
// proj via mma: CTA = 128 oc x 128 px (one row), K=128. Writes d_out.
// ---------------------------------------------------------------------------
#define PROJ_SMEM 65536
__global__ __launch_bounds__(256) void proj_mma_kernel(
    const float* __restrict__ ppan_b, const float* __restrict__ pms_b,
    float* __restrict__ out)
{
    extern __shared__ char psm[];
    int t = threadIdx.x, w = t >> 5, lane = t & 31;
    int g = lane >> 2, tt = lane & 3;
    int mw0 = (w >> 2) * 4, n80 = (w & 3) * 4;
    int row = blockIdx.x, sidx = blockIdx.y, b = blockIdx.z;
    uint32_t sb = (uint32_t)__cvta_generic_to_shared(psm);

    // A: 32KB, B: 32KB
    const char* Asrc = (const char*)(g_WPh + (size_t)sidx * 16384);
#pragma unroll
    for (int j = 0; j < 8; j++) cp16(sb + t * 128 + j * 16, Asrc + t * 128 + j * 16);
    {
        int px = t >> 1;
        int kh = (t & 1) * 4;
        const char* Bsrc = (const char*)(g_ATTh +
            ((size_t)(b * 2 + sidx) * HW + row * 128 + px) * 128);
#pragma unroll
        for (int k16 = 0; k16 < 4; k16++) {
            uint32_t d = sb + 32768 + (kh + k16) * 4096 + px * 32;
            cp16(d,      Bsrc + (kh + k16) * 32);
            cp16(d + 16, Bsrc + (kh + k16) * 32 + 16);
        }
    }
    asm volatile("cp.async.commit_group;" ::: "memory");
    asm volatile("cp.async.wait_group 0;" ::: "memory");
    __syncthreads();

    float acc[4][4][4];
#pragma unroll
    for (int mf = 0; mf < 4; mf++)
#pragma unroll
        for (int nf = 0; nf < 4; nf++)
#pragma unroll
            for (int r = 0; r < 4; r++) acc[mf][nf][r] = 0.0f;

#pragma unroll
    for (int k16 = 0; k16 < 8; k16++) {
        uint32_t a[4][4];
#pragma unroll
        for (int mf = 0; mf < 4; mf++) {
            uint32_t addr = sb + k16 * 4096 + (mw0 + mf) * 512 + lane * 16;
            asm volatile("ld.shared.v4.u32 {%0,%1,%2,%3}, [%4];"
                : "=r"(a[mf][0]), "=r"(a[mf][1]), "=r"(a[mf][2]), "=r"(a[mf][3])
                : "r"(addr));
        }
        uint32_t b0[4], b1[4];
#pragma unroll
        for (int nf = 0; nf < 4; nf++) {
            uint32_t addr = sb + 32768 + k16 * 4096 + (((n80 + nf) * 8 + g) * 32) + tt * 8;
            asm volatile("ld.shared.v2.u32 {%0,%1}, [%2];"
                : "=r"(b0[nf]), "=r"(b1[nf]) : "r"(addr));
        }
#pragma unroll
        for (int mf = 0; mf < 4; mf++)
#pragma unroll
            for (int nf = 0; nf < 4; nf++)
                mma_f16(acc[mf][nf], a[mf], b0[nf], b1[nf]);
    }

    const float* bp = sidx ? pms_b : ppan_b;
    float* obase = out + (size_t)sidx * BB * DIM * HW;
#pragma unroll
    for (int mf = 0; mf < 4; mf++) {
        int oc = (mw0 + mf) * 16 + g;
        float b0v = bp[oc];
        float b1v = bp[oc + 8];
        float* r0 = obase + ((size_t)(b * DIM + oc)) * HW + row * WW;
        float* r1 = r0 + (size_t)8 * HW;
#pragma unroll
        for (int nf = 0; nf < 4; nf++) {
            int nn = (n80 + nf) * 8 + tt * 2;
            float2 o0, o1;
            o0.x = acc[mf][nf][0] + b0v;
            o0.y = acc[mf][nf][1] + b0v;
            o1.x = acc[mf][nf][2] + b1v;
            o1.y = acc[mf][nf][3] + b1v;
            *(float2*)(r0 + nn) = o0;
            *(float2*)(r1 + nn) = o1;
        }
    }
}

// ---------------------------------------------------------------------------
extern "C" void kernel_launch(void* const* d_in, const int* in_sizes, int n_in,
                              void* d_out, int out_size)
{
    const float* x        = (const float*)d_in[0];
    const float* ms       = (const float*)d_in[1];
    const float* lpan     = (const float*)d_in[2];
    const float* pan      = (const float*)d_in[3];
    const float* s        = (const float*)d_in[4];
    const float* q_w      = (const float*)d_in[5];
    const float* q_b      = (const float*)d_in[6];
    const float* k_pan_w  = (const float*)d_in[7];
    const float* k_pan_b  = (const float*)d_in[8];
    const float* v_pan_w  = (const float*)d_in[9];
    const float* v_pan_b  = (const float*)d_in[10];
    const float* kv_ms_w  = (const float*)d_in[11];
    const float* kv_ms_b  = (const float*)d_in[12];
    const float* dep_w    = (const float*)d_in[13];
    const float* dep_b    = (const float*)d_in[14];
    const float* ppan_w   = (const float*)d_in[15];
    const float* ppan_b   = (const float*)d_in[16];
    const float* pms_w    = (const float*)d_in[17];
    const float* pms_b    = (const float*)d_in[18];
    float* out = (float*)d_out;

    cudaFuncSetAttribute(conv_mma_kernel,
                         cudaFuncAttributeMaxDynamicSharedMemorySize, CONV_SMEM);
    cudaFuncSetAttribute(proj_mma_kernel,
                         cudaFuncAttributeMaxDynamicSharedMemorySize, PROJ_SMEM);

    dim3 xg(HW / 64, BB);
    build_xt_kernel<<<xg, 256>>>(x, ms, lpan, pan, s);
    zero_border_kernel<<<(BB * NPIX + 255) / 256, 256>>>();
    repack_w_kernel<<<(5 * 45 * 4096 + 255) / 256, 256>>>(
        q_w, k_pan_w, v_pan_w, kv_ms_w, q_b, k_pan_b, v_pan_b, kv_ms_b);
    repack_proj_kernel<<<(2 * 16384 + 255) / 256, 256>>>(ppan_w, pms_w);

    dim3 cg(HH, 5, BB);
    conv_mma_kernel<<<cg, 256, CONV_SMEM>>>();

    dim3 ag(16, 16, BB);
    attn_kernel<<<ag, 256>>>(dep_w, dep_b);

    dim3 pj(HH, 2, BB);
    proj_mma_kernel<<<pj, 256, PROJ_SMEM>>>(ppan_b, pms_b, out);
}